// round 1
// baseline (speedup 1.0000x reference)
#include <cuda_runtime.h>
#include <math.h>

#define RK 3
#define NN 300000
#define HH 256
#define GG 2048
#define TOT (RK*NN)

// ---------------- scratch (no allocations allowed) ----------------
__device__ float    g_s[TOT];                      // scores, then exp(s-m) in place
__device__ unsigned g_menc[RK*GG];                 // ordered-uint encoded segment max of s
__device__ float    g_denom[RK*GG];                // softmax denominators
__device__ float    g_cnt[RK*GG];                  // node counts per graph
__device__ float    g_agg[(size_t)RK*GG*4*HH];     // [r][g][0:H)=sum [H:2H)=mean [2H:3H)=max [3H:4H)=att
__device__ float    g_rv[(size_t)RK*GG*HH];        // rank_proj outputs

__device__ __forceinline__ unsigned fenc(float f){
    unsigned b = __float_as_uint(f);
    return (b & 0x80000000u) ? ~b : (b | 0x80000000u);
}
__device__ __forceinline__ float fdec(unsigned u){
    return (u & 0x80000000u) ? __uint_as_float(u & 0x7fffffffu) : __uint_as_float(~u);
}
__device__ __forceinline__ float siluf(float x){ return x / (1.f + expf(-x)); }

// ---------------- 0: zero scratch ----------------
__global__ void zero_kernel(){
    int i = blockIdx.x * 256 + threadIdx.x;
    if (i < RK*GG*HH) ((float4*)g_agg)[i] = make_float4(0.f,0.f,0.f,0.f); // = RK*GG*4*HH floats
    if (i < RK*GG){ g_menc[i] = 0u; g_denom[i] = 0.f; g_cnt[i] = 0.f; }
}

// ---------------- 1: score GEMM: s = tanh(h@W1+b1)@w2 + b2 ----------------
// 64x256 tile, K=256 in chunks of 8, 256 threads, 8x8 microtile.
__global__ __launch_bounds__(256) void score_gemm(
    const float* __restrict__ h, const float* __restrict__ W1,
    const float* __restrict__ b1, const float* __restrict__ w2,
    const float* __restrict__ b2)
{
    const int r  = blockIdx.y;
    const int n0 = blockIdx.x * 64;
    const float* hb = h  + (size_t)r*NN*HH;
    const float* Wb = W1 + (size_t)r*HH*HH;

    __shared__ float As[8][64];
    __shared__ float Bs[8][256];

    const int tid = threadIdx.x;
    const int ry  = tid >> 5;        // warp = row group (rows ry*8..+8)
    const int cx  = tid & 31;        // lane = col group (cols cx*4..+4 and 128+cx*4..+4)

    const int la_row = tid >> 2;           // 0..63
    const int la_k   = (tid & 3) * 2;      // 0,2,4,6
    const int lb_k   = tid >> 5;           // 0..7
    const int lb_col = (tid & 31) * 8;     // 0..248

    float acc[8][8];
    #pragma unroll
    for (int i = 0; i < 8; i++)
        #pragma unroll
        for (int j = 0; j < 8; j++) acc[i][j] = 0.f;

    for (int k0 = 0; k0 < HH; k0 += 8){
        float2 av = make_float2(0.f, 0.f);
        int arow = n0 + la_row;
        if (arow < NN) av = *(const float2*)(hb + (size_t)arow*HH + k0 + la_k);
        float4 bv0 = *(const float4*)(Wb + (size_t)(k0 + lb_k)*HH + lb_col);
        float4 bv1 = *(const float4*)(Wb + (size_t)(k0 + lb_k)*HH + lb_col + 4);
        __syncthreads();
        As[la_k][la_row]     = av.x;
        As[la_k + 1][la_row] = av.y;
        *(float4*)&Bs[lb_k][lb_col]     = bv0;
        *(float4*)&Bs[lb_k][lb_col + 4] = bv1;
        __syncthreads();
        #pragma unroll
        for (int kk = 0; kk < 8; kk++){
            float4 a0 = *(const float4*)&As[kk][ry*8];
            float4 a1 = *(const float4*)&As[kk][ry*8 + 4];
            float4 b0 = *(const float4*)&Bs[kk][cx*4];
            float4 b1v = *(const float4*)&Bs[kk][128 + cx*4];
            float a[8] = {a0.x,a0.y,a0.z,a0.w,a1.x,a1.y,a1.z,a1.w};
            float b[8] = {b0.x,b0.y,b0.z,b0.w,b1v.x,b1v.y,b1v.z,b1v.w};
            #pragma unroll
            for (int i = 0; i < 8; i++)
                #pragma unroll
                for (int j = 0; j < 8; j++) acc[i][j] += a[i] * b[j];
        }
    }

    // epilogue: tanh + dot w2 + warp reduce over cols
    float b1v[8], w2v[8];
    #pragma unroll
    for (int j = 0; j < 8; j++){
        int col = (j < 4) ? (cx*4 + j) : (128 + cx*4 + (j - 4));
        b1v[j] = b1[r*HH + col];
        w2v[j] = w2[r*HH + col];
    }
    float b2v = b2[r];
    #pragma unroll
    for (int i = 0; i < 8; i++){
        float p = 0.f;
        #pragma unroll
        for (int j = 0; j < 8; j++) p += tanhf(acc[i][j] + b1v[j]) * w2v[j];
        #pragma unroll
        for (int o = 16; o > 0; o >>= 1) p += __shfl_xor_sync(0xffffffffu, p, o);
        int row = n0 + ry*8 + i;
        if (cx == 0 && row < NN) g_s[(size_t)r*NN + row] = p + b2v;
    }
}

// ---------------- 2: segment max of s ----------------
__global__ void seg_max_kernel(const int* __restrict__ batch){
    int idx = blockIdx.x * 256 + threadIdx.x;
    if (idx >= TOT) return;
    int r = idx / NN;
    int g = batch[idx];
    atomicMax(&g_menc[r*GG + g], fenc(g_s[idx]));
}

// ---------------- 3: e = exp(s - m); denom += e ----------------
__global__ void seg_exp_kernel(const int* __restrict__ batch){
    int idx = blockIdx.x * 256 + threadIdx.x;
    if (idx >= TOT) return;
    int r = idx / NN;
    int g = batch[idx];
    float m = fdec(g_menc[r*GG + g]);
    float e = expf(g_s[idx] - m);
    g_s[idx] = e;
    atomicAdd(&g_denom[r*GG + g], e);
}

// ---------------- 4: pools (sum / max / att) using sorted batch ----------------
#define CHUNK 256
__global__ __launch_bounds__(256) void pool_kernel(
    const float* __restrict__ h, const int* __restrict__ batch)
{
    __shared__ int   sseg[CHUNK];
    __shared__ float sa[CHUNK];
    const int tid = threadIdx.x;
    const long base = (long)blockIdx.x * CHUNK;

    {
        long idx = base + tid;
        int seg = -1; float a = 0.f;
        if (idx < TOT){
            int r = (int)(idx / NN);
            int g = batch[idx];
            seg = r*GG + g;
            a = g_s[idx] / g_denom[seg];
        }
        sseg[tid] = seg; sa[tid] = a;
    }
    __syncthreads();

    const int col = tid;                 // H == blockDim
    float vs = 0.f, va = 0.f, vm = -INFINITY;
    int cnt_local = 0;
    int curseg = sseg[0];

    for (int j = 0; j < CHUNK; j += 4){
        float hv[4];
        #pragma unroll
        for (int u = 0; u < 4; u++){
            long idx = base + j + u;
            hv[u] = (idx < TOT) ? h[idx*HH + col] : 0.f;
        }
        #pragma unroll
        for (int u = 0; u < 4; u++){
            int sg = sseg[j + u];
            if (sg < 0) continue;
            if (sg != curseg){
                if (cnt_local > 0){
                    float* ag = g_agg + (size_t)curseg*4*HH;
                    atomicAdd(&ag[col], vs);
                    atomicAdd(&ag[3*HH + col], va);
                    atomicMax((unsigned*)&ag[2*HH + col], fenc(vm));
                    if (col == 0) atomicAdd(&g_cnt[curseg], (float)cnt_local);
                }
                vs = 0.f; va = 0.f; vm = -INFINITY; cnt_local = 0;
                curseg = sg;
            }
            vs += hv[u];
            va += sa[j + u] * hv[u];
            vm = fmaxf(vm, hv[u]);
            cnt_local++;
        }
    }
    if (curseg >= 0 && cnt_local > 0){
        float* ag = g_agg + (size_t)curseg*4*HH;
        atomicAdd(&ag[col], vs);
        atomicAdd(&ag[3*HH + col], va);
        atomicMax((unsigned*)&ag[2*HH + col], fenc(vm));
        if (col == 0) atomicAdd(&g_cnt[curseg], (float)cnt_local);
    }
}

// ---------------- 5: finalize agg (mean, decode max) ----------------
__global__ void finalize_kernel(){
    int idx = blockIdx.x * 256 + threadIdx.x;
    if (idx >= RK*GG*HH) return;
    int seg = idx / HH;
    int col = idx - seg*HH;
    float c = g_cnt[seg];
    float* ag = g_agg + (size_t)seg*4*HH;
    ag[HH + col] = ag[col] / fmaxf(c, 1.f);
    unsigned u = __float_as_uint(ag[2*HH + col]);
    ag[2*HH + col] = (c > 0.f) ? fdec(u) : 0.f;
}

// ---------------- 6: rv = agg @ Wp + bp  (per rank 2048x256x1024 GEMM) ----------------
__global__ __launch_bounds__(256) void rv_gemm(
    const float* __restrict__ Wp, const float* __restrict__ bp)
{
    const int r  = blockIdx.y;
    const int g0 = blockIdx.x * 64;
    const float* Ab = g_agg + (size_t)r*GG*4*HH;     // [G][1024]
    const float* Wb = Wp    + (size_t)r*4*HH*HH;     // [1024][256]

    __shared__ float As[8][64];
    __shared__ float Bs[8][256];

    const int tid = threadIdx.x;
    const int ry  = tid >> 5;
    const int cx  = tid & 31;
    const int la_row = tid >> 2;
    const int la_k   = (tid & 3) * 2;
    const int lb_k   = tid >> 5;
    const int lb_col = (tid & 31) * 8;

    float acc[8][8];
    #pragma unroll
    for (int i = 0; i < 8; i++)
        #pragma unroll
        for (int j = 0; j < 8; j++) acc[i][j] = 0.f;

    for (int k0 = 0; k0 < 4*HH; k0 += 8){
        float2 av  = *(const float2*)(Ab + (size_t)(g0 + la_row)*4*HH + k0 + la_k);
        float4 bv0 = *(const float4*)(Wb + (size_t)(k0 + lb_k)*HH + lb_col);
        float4 bv1 = *(const float4*)(Wb + (size_t)(k0 + lb_k)*HH + lb_col + 4);
        __syncthreads();
        As[la_k][la_row]     = av.x;
        As[la_k + 1][la_row] = av.y;
        *(float4*)&Bs[lb_k][lb_col]     = bv0;
        *(float4*)&Bs[lb_k][lb_col + 4] = bv1;
        __syncthreads();
        #pragma unroll
        for (int kk = 0; kk < 8; kk++){
            float4 a0 = *(const float4*)&As[kk][ry*8];
            float4 a1 = *(const float4*)&As[kk][ry*8 + 4];
            float4 b0 = *(const float4*)&Bs[kk][cx*4];
            float4 b1v = *(const float4*)&Bs[kk][128 + cx*4];
            float a[8] = {a0.x,a0.y,a0.z,a0.w,a1.x,a1.y,a1.z,a1.w};
            float b[8] = {b0.x,b0.y,b0.z,b0.w,b1v.x,b1v.y,b1v.z,b1v.w};
            #pragma unroll
            for (int i = 0; i < 8; i++)
                #pragma unroll
                for (int j = 0; j < 8; j++) acc[i][j] += a[i] * b[j];
        }
    }

    #pragma unroll
    for (int i = 0; i < 8; i++){
        int row = g0 + ry*8 + i;
        #pragma unroll
        for (int j = 0; j < 8; j++){
            int col = (j < 4) ? (cx*4 + j) : (128 + cx*4 + (j - 4));
            g_rv[((size_t)r*GG + row)*HH + col] = acc[i][j] + bp[r*HH + col];
        }
    }
}

// ---------------- 7: final MLP: LN -> SiLU -> Wf1 -> SiLU -> Wf2 ----------------
__global__ __launch_bounds__(256) void final_mlp(
    const float* __restrict__ ln_g, const float* __restrict__ ln_b,
    const float* __restrict__ Wf1,  const float* __restrict__ bf1,
    const float* __restrict__ Wf2,  const float* __restrict__ bf2,
    float* __restrict__ out)
{
    __shared__ float st[4][3*HH];   // state, then y=silu(LN(state)) in place
    __shared__ float ws[8], wq[8];
    __shared__ float red[4][8];

    const int tid  = threadIdx.x;
    const int lane = tid & 31;
    const int wrp  = tid >> 5;
    const int g0   = blockIdx.x * 4;

    for (int t = tid; t < 4*3*HH; t += 256){
        int gg = t / (3*HH);
        int k  = t - gg*3*HH;
        int r  = k >> 8;
        int j  = k & 255;
        st[gg][k] = g_rv[((size_t)r*GG + g0 + gg)*HH + j];
    }
    __syncthreads();

    // LayerNorm + first SiLU, per graph
    for (int gg = 0; gg < 4; gg++){
        float v0 = st[gg][tid], v1 = st[gg][tid + 256], v2 = st[gg][tid + 512];
        float sm = v0 + v1 + v2;
        float sq = v0*v0 + v1*v1 + v2*v2;
        #pragma unroll
        for (int o = 16; o > 0; o >>= 1){
            sm += __shfl_xor_sync(0xffffffffu, sm, o);
            sq += __shfl_xor_sync(0xffffffffu, sq, o);
        }
        if (lane == 0){ ws[wrp] = sm; wq[wrp] = sq; }
        __syncthreads();
        float tm = 0.f, tq = 0.f;
        #pragma unroll
        for (int w = 0; w < 8; w++){ tm += ws[w]; tq += wq[w]; }
        float mu   = tm / (3.f*HH);
        float var  = tq / (3.f*HH) - mu*mu;
        float rstd = rsqrtf(var + 1e-5f);
        st[gg][tid]       = siluf((v0 - mu)*rstd*ln_g[tid]       + ln_b[tid]);
        st[gg][tid + 256] = siluf((v1 - mu)*rstd*ln_g[tid + 256] + ln_b[tid + 256]);
        st[gg][tid + 512] = siluf((v2 - mu)*rstd*ln_g[tid + 512] + ln_b[tid + 512]);
        __syncthreads();
    }

    // z_j = silu(y @ Wf1 + bf1), then out = z @ Wf2 + bf2
    float acc[4];
    float bz = bf1[tid];
    #pragma unroll
    for (int gg = 0; gg < 4; gg++) acc[gg] = bz;
    for (int k = 0; k < 3*HH; k++){
        float w = Wf1[k*HH + tid];
        #pragma unroll
        for (int gg = 0; gg < 4; gg++) acc[gg] += st[gg][k] * w;
    }
    float w2v = Wf2[tid];
    #pragma unroll
    for (int gg = 0; gg < 4; gg++){
        float z = siluf(acc[gg]) * w2v;
        #pragma unroll
        for (int o = 16; o > 0; o >>= 1) z += __shfl_xor_sync(0xffffffffu, z, o);
        if (lane == 0) red[gg][wrp] = z;
    }
    __syncthreads();
    if (tid < 4){
        float o = bf2[0];
        #pragma unroll
        for (int w = 0; w < 8; w++) o += red[tid][w];
        out[g0 + tid] = o;
    }
}

// ---------------- launch ----------------
extern "C" void kernel_launch(void* const* d_in, const int* in_sizes, int n_in,
                              void* d_out, int out_size)
{
    const float* h     = (const float*)d_in[0];
    const int*   batch = (const int*)  d_in[1];
    const float* W1    = (const float*)d_in[2];
    const float* b1    = (const float*)d_in[3];
    const float* w2    = (const float*)d_in[4];
    const float* b2    = (const float*)d_in[5];
    const float* Wp    = (const float*)d_in[6];
    const float* bp    = (const float*)d_in[7];
    const float* ln_g  = (const float*)d_in[8];
    const float* ln_b  = (const float*)d_in[9];
    const float* Wf1   = (const float*)d_in[10];
    const float* bf1   = (const float*)d_in[11];
    const float* Wf2   = (const float*)d_in[12];
    const float* bf2   = (const float*)d_in[13];
    float* out = (float*)d_out;

    zero_kernel<<<(RK*GG*HH + 255)/256, 256>>>();
    score_gemm<<<dim3((NN + 63)/64, RK), 256>>>(h, W1, b1, w2, b2);
    seg_max_kernel<<<(TOT + 255)/256, 256>>>(batch);
    seg_exp_kernel<<<(TOT + 255)/256, 256>>>(batch);
    pool_kernel<<<(TOT + CHUNK - 1)/CHUNK, 256>>>(h, batch);
    finalize_kernel<<<(RK*GG*HH + 255)/256, 256>>>();
    rv_gemm<<<dim3(GG/64, RK), 256>>>(Wp, bp);
    final_mlp<<<GG/4, 256>>>(ln_g, ln_b, Wf1, bf1, Wf2, bf2, out);
}

// round 3
// speedup vs baseline: 1.1965x; 1.1965x over previous
#include <cuda_runtime.h>
#include <math.h>

#define RK 3
#define NN 300000
#define HH 256
#define GG 2048
#define TOT (RK*NN)

// ---------------- scratch (no allocations allowed) ----------------
__device__ float    g_s[TOT];                      // scores, then exp(s-m) in place
__device__ unsigned g_menc[RK*GG];                 // ordered-uint encoded segment max of s
__device__ float    g_denom[RK*GG];                // softmax denominators
__device__ float    g_cnt[RK*GG];                  // node counts per graph
__device__ float    g_agg[(size_t)RK*GG*4*HH];     // [r][g][0:H)=sum [H:2H)=mean [2H:3H)=max [3H:4H)=att
__device__ float    g_rv[(size_t)RK*GG*HH];        // rank_proj outputs

__device__ __forceinline__ unsigned fenc(float f){
    unsigned b = __float_as_uint(f);
    return (b & 0x80000000u) ? ~b : (b | 0x80000000u);
}
__device__ __forceinline__ float fdec(unsigned u){
    return (u & 0x80000000u) ? __uint_as_float(u & 0x7fffffffu) : __uint_as_float(~u);
}
__device__ __forceinline__ float siluf(float x){ return x / (1.f + expf(-x)); }

__device__ __forceinline__ unsigned to_tf32(float f){
    unsigned r;
    asm("cvt.rna.tf32.f32 %0, %1;" : "=r"(r) : "f"(f));
    return r;
}

__device__ __forceinline__ void mma_tf32(float* c, const unsigned* a, const unsigned* b){
    asm volatile(
        "mma.sync.aligned.m16n8k8.row.col.f32.tf32.tf32.f32 "
        "{%0,%1,%2,%3}, {%4,%5,%6,%7}, {%8,%9}, {%0,%1,%2,%3};"
        : "+f"(c[0]), "+f"(c[1]), "+f"(c[2]), "+f"(c[3])
        : "r"(a[0]), "r"(a[1]), "r"(a[2]), "r"(a[3]), "r"(b[0]), "r"(b[1]));
}

// ---------------- 0: zero scratch ----------------
__global__ void zero_kernel(){
    int i = blockIdx.x * 256 + threadIdx.x;
    if (i < RK*GG*HH) ((float4*)g_agg)[i] = make_float4(0.f,0.f,0.f,0.f); // = RK*GG*4*HH floats
    if (i < RK*GG){ g_menc[i] = 0u; g_denom[i] = 0.f; g_cnt[i] = 0.f; }
}

// ---------------- 1: score GEMM (tf32 tensor cores) ----------------
// s = tanh(h@W1 + b1)@w2 + b2
// Block: 64 rows x 256 cols, BK=16, 8 warps (2x4), warp tile 32x64 (2x8 m16n8k8).
#define AST 68   // As row stride ([k][m])
#define BST 260  // Bs row stride ([k][n])
__global__ __launch_bounds__(256, 2) void score_gemm(
    const float* __restrict__ h, const float* __restrict__ W1,
    const float* __restrict__ b1, const float* __restrict__ w2,
    const float* __restrict__ b2)
{
    const int r  = blockIdx.y;
    const int n0 = blockIdx.x * 64;                  // row (node) base
    const float* hb = h  + (size_t)r*NN*HH;
    const float* Wb = W1 + (size_t)r*HH*HH;

    __shared__ unsigned As[16*AST];                  // As[k][m], tf32 bits
    __shared__ unsigned Bs[16*BST];                  // Bs[k][n], tf32 bits
    __shared__ float    s_row[64];

    const int tid   = threadIdx.x;
    const int lane  = tid & 31;
    const int warp  = tid >> 5;
    const int warpM = warp >> 2;                     // 0..1 -> rows warpM*32
    const int warpN = warp & 3;                      // 0..3 -> cols warpN*64
    const int lg    = lane >> 2;                     // group id 0..7
    const int lt    = lane & 3;                      // thread-in-group 0..3

    // global load assignment
    const int a_row = tid >> 2;                      // 0..63
    const int a_k   = (tid & 3) * 4;                 // 0,4,8,12
    const int b_k0  = tid >> 6;                      // 0..3 (row = b_k0 + i*4)
    const int b_n   = (tid & 63) * 4;                // 0..252

    const bool a_ok = (n0 + a_row) < NN;

    float acc[2][8][4];
    #pragma unroll
    for (int mt = 0; mt < 2; mt++)
        #pragma unroll
        for (int nt = 0; nt < 8; nt++)
            #pragma unroll
            for (int j = 0; j < 4; j++) acc[mt][nt][j] = 0.f;

    // prefetch k-tile 0
    float4 aval = make_float4(0.f,0.f,0.f,0.f);
    if (a_ok) aval = *(const float4*)(hb + (size_t)(n0 + a_row)*HH + a_k);
    float4 bval[4];
    #pragma unroll
    for (int i = 0; i < 4; i++)
        bval[i] = *(const float4*)(Wb + (size_t)(b_k0 + i*4)*HH + b_n);

    for (int kt = 0; kt < 16; kt++){
        __syncthreads();
        // store tile (transpose A to [k][m], keep B [k][n]) with tf32 rounding
        As[(a_k+0)*AST + a_row] = to_tf32(aval.x);
        As[(a_k+1)*AST + a_row] = to_tf32(aval.y);
        As[(a_k+2)*AST + a_row] = to_tf32(aval.z);
        As[(a_k+3)*AST + a_row] = to_tf32(aval.w);
        #pragma unroll
        for (int i = 0; i < 4; i++){
            unsigned* p = &Bs[(b_k0 + i*4)*BST + b_n];
            p[0] = to_tf32(bval[i].x);
            p[1] = to_tf32(bval[i].y);
            p[2] = to_tf32(bval[i].z);
            p[3] = to_tf32(bval[i].w);
        }
        __syncthreads();

        // prefetch next k-tile
        if (kt < 15){
            int k0 = (kt + 1) * 16;
            if (a_ok) aval = *(const float4*)(hb + (size_t)(n0 + a_row)*HH + k0 + a_k);
            #pragma unroll
            for (int i = 0; i < 4; i++)
                bval[i] = *(const float4*)(Wb + (size_t)(k0 + b_k0 + i*4)*HH + b_n);
        }

        // compute: 2 k8 steps x 16 mma
        #pragma unroll
        for (int ks = 0; ks < 2; ks++){
            const int kb = ks * 8;
            unsigned afr[2][4], bfr[8][2];
            #pragma unroll
            for (int mt = 0; mt < 2; mt++){
                int m = warpM*32 + mt*16;
                afr[mt][0] = As[(kb + lt    )*AST + m + lg    ];
                afr[mt][1] = As[(kb + lt    )*AST + m + lg + 8];
                afr[mt][2] = As[(kb + lt + 4)*AST + m + lg    ];
                afr[mt][3] = As[(kb + lt + 4)*AST + m + lg + 8];
            }
            #pragma unroll
            for (int nt = 0; nt < 8; nt++){
                int n = warpN*64 + nt*8;
                bfr[nt][0] = Bs[(kb + lt    )*BST + n + lg];
                bfr[nt][1] = Bs[(kb + lt + 4)*BST + n + lg];
            }
            #pragma unroll
            for (int mt = 0; mt < 2; mt++)
                #pragma unroll
                for (int nt = 0; nt < 8; nt++)
                    mma_tf32(acc[mt][nt], afr[mt], bfr[nt]);
        }
    }

    // ---------------- epilogue: tanh + dot(w2) + row reduce ----------------
    __syncthreads();
    if (tid < 64) s_row[tid] = 0.f;
    __syncthreads();

    // per-thread columns: warpN*64 + nt*8 + lt*2 + {0,1}
    float b1v[16], w2v[16];
    #pragma unroll
    for (int nt = 0; nt < 8; nt++){
        int c0 = warpN*64 + nt*8 + lt*2;
        b1v[nt*2]   = b1[r*HH + c0];
        b1v[nt*2+1] = b1[r*HH + c0 + 1];
        w2v[nt*2]   = w2[r*HH + c0];
        w2v[nt*2+1] = w2[r*HH + c0 + 1];
    }

    #pragma unroll
    for (int mt = 0; mt < 2; mt++){
        float pA = 0.f, pB = 0.f;   // rows base+lg and base+lg+8
        #pragma unroll
        for (int nt = 0; nt < 8; nt++){
            pA += tanhf(acc[mt][nt][0] + b1v[nt*2  ]) * w2v[nt*2  ];
            pA += tanhf(acc[mt][nt][1] + b1v[nt*2+1]) * w2v[nt*2+1];
            pB += tanhf(acc[mt][nt][2] + b1v[nt*2  ]) * w2v[nt*2  ];
            pB += tanhf(acc[mt][nt][3] + b1v[nt*2+1]) * w2v[nt*2+1];
        }
        // reduce over the 4-lane column group (lt)
        #pragma unroll
        for (int o = 1; o < 4; o <<= 1){
            pA += __shfl_xor_sync(0xffffffffu, pA, o);
            pB += __shfl_xor_sync(0xffffffffu, pB, o);
        }
        if (lt == 0){
            int rbase = warpM*32 + mt*16 + lg;
            atomicAdd(&s_row[rbase    ], pA);
            atomicAdd(&s_row[rbase + 8], pB);
        }
    }
    __syncthreads();

    if (tid < 64){
        int row = n0 + tid;
        if (row < NN) g_s[(size_t)r*NN + row] = s_row[tid] + b2[r];
    }
}

// ---------------- 2: segment max of s ----------------
__global__ void seg_max_kernel(const int* __restrict__ batch){
    int idx = blockIdx.x * 256 + threadIdx.x;
    if (idx >= TOT) return;
    int r = idx / NN;
    int g = batch[idx];
    atomicMax(&g_menc[r*GG + g], fenc(g_s[idx]));
}

// ---------------- 3: e = exp(s - m); denom += e ----------------
__global__ void seg_exp_kernel(const int* __restrict__ batch){
    int idx = blockIdx.x * 256 + threadIdx.x;
    if (idx >= TOT) return;
    int r = idx / NN;
    int g = batch[idx];
    float m = fdec(g_menc[r*GG + g]);
    float e = expf(g_s[idx] - m);
    g_s[idx] = e;
    atomicAdd(&g_denom[r*GG + g], e);
}

// ---------------- 4: pools (sum / max / att) using sorted batch ----------------
#define CHUNK 256
__global__ __launch_bounds__(256) void pool_kernel(
    const float* __restrict__ h, const int* __restrict__ batch)
{
    __shared__ int   sseg[CHUNK];
    __shared__ float sa[CHUNK];
    const int tid = threadIdx.x;
    const long base = (long)blockIdx.x * CHUNK;

    {
        long idx = base + tid;
        int seg = -1; float a = 0.f;
        if (idx < TOT){
            int r = (int)(idx / NN);
            int g = batch[idx];
            seg = r*GG + g;
            a = g_s[idx] / g_denom[seg];
        }
        sseg[tid] = seg; sa[tid] = a;
    }
    __syncthreads();

    const int col = tid;                 // H == blockDim
    float vs = 0.f, va = 0.f, vm = -INFINITY;
    int cnt_local = 0;
    int curseg = sseg[0];

    for (int j = 0; j < CHUNK; j += 4){
        float hv[4];
        #pragma unroll
        for (int u = 0; u < 4; u++){
            long idx = base + j + u;
            hv[u] = (idx < TOT) ? h[idx*HH + col] : 0.f;
        }
        #pragma unroll
        for (int u = 0; u < 4; u++){
            int sg = sseg[j + u];
            if (sg < 0) continue;
            if (sg != curseg){
                if (cnt_local > 0){
                    float* ag = g_agg + (size_t)curseg*4*HH;
                    atomicAdd(&ag[col], vs);
                    atomicAdd(&ag[3*HH + col], va);
                    atomicMax((unsigned*)&ag[2*HH + col], fenc(vm));
                    if (col == 0) atomicAdd(&g_cnt[curseg], (float)cnt_local);
                }
                vs = 0.f; va = 0.f; vm = -INFINITY; cnt_local = 0;
                curseg = sg;
            }
            vs += hv[u];
            va += sa[j + u] * hv[u];
            vm = fmaxf(vm, hv[u]);
            cnt_local++;
        }
    }
    if (curseg >= 0 && cnt_local > 0){
        float* ag = g_agg + (size_t)curseg*4*HH;
        atomicAdd(&ag[col], vs);
        atomicAdd(&ag[3*HH + col], va);
        atomicMax((unsigned*)&ag[2*HH + col], fenc(vm));
        if (col == 0) atomicAdd(&g_cnt[curseg], (float)cnt_local);
    }
}

// ---------------- 5: finalize agg (mean, decode max) ----------------
__global__ void finalize_kernel(){
    int idx = blockIdx.x * 256 + threadIdx.x;
    if (idx >= RK*GG*HH) return;
    int seg = idx / HH;
    int col = idx - seg*HH;
    float c = g_cnt[seg];
    float* ag = g_agg + (size_t)seg*4*HH;
    ag[HH + col] = ag[col] / fmaxf(c, 1.f);
    unsigned u = __float_as_uint(ag[2*HH + col]);
    ag[2*HH + col] = (c > 0.f) ? fdec(u) : 0.f;
}

// ---------------- 6: rv = agg @ Wp + bp  (per rank 2048x256x1024 GEMM) ----------------
__global__ __launch_bounds__(256) void rv_gemm(
    const float* __restrict__ Wp, const float* __restrict__ bp)
{
    const int r  = blockIdx.y;
    const int g0 = blockIdx.x * 64;
    const float* Ab = g_agg + (size_t)r*GG*4*HH;     // [G][1024]
    const float* Wb = Wp    + (size_t)r*4*HH*HH;     // [1024][256]

    __shared__ float As2[8][64];
    __shared__ float Bs2[8][256];

    const int tid = threadIdx.x;
    const int ry  = tid >> 5;
    const int cx  = tid & 31;
    const int la_row = tid >> 2;
    const int la_k   = (tid & 3) * 2;
    const int lb_k   = tid >> 5;
    const int lb_col = (tid & 31) * 8;

    float acc[8][8];
    #pragma unroll
    for (int i = 0; i < 8; i++)
        #pragma unroll
        for (int j = 0; j < 8; j++) acc[i][j] = 0.f;

    for (int k0 = 0; k0 < 4*HH; k0 += 8){
        float2 av  = *(const float2*)(Ab + (size_t)(g0 + la_row)*4*HH + k0 + la_k);
        float4 bv0 = *(const float4*)(Wb + (size_t)(k0 + lb_k)*HH + lb_col);
        float4 bv1 = *(const float4*)(Wb + (size_t)(k0 + lb_k)*HH + lb_col + 4);
        __syncthreads();
        As2[la_k][la_row]     = av.x;
        As2[la_k + 1][la_row] = av.y;
        *(float4*)&Bs2[lb_k][lb_col]     = bv0;
        *(float4*)&Bs2[lb_k][lb_col + 4] = bv1;
        __syncthreads();
        #pragma unroll
        for (int kk = 0; kk < 8; kk++){
            float4 a0 = *(const float4*)&As2[kk][ry*8];
            float4 a1 = *(const float4*)&As2[kk][ry*8 + 4];
            float4 b0 = *(const float4*)&Bs2[kk][cx*4];
            float4 b1v = *(const float4*)&Bs2[kk][128 + cx*4];
            float a[8] = {a0.x,a0.y,a0.z,a0.w,a1.x,a1.y,a1.z,a1.w};
            float b[8] = {b0.x,b0.y,b0.z,b0.w,b1v.x,b1v.y,b1v.z,b1v.w};
            #pragma unroll
            for (int i = 0; i < 8; i++)
                #pragma unroll
                for (int j = 0; j < 8; j++) acc[i][j] += a[i] * b[j];
        }
    }

    #pragma unroll
    for (int i = 0; i < 8; i++){
        int row = g0 + ry*8 + i;
        #pragma unroll
        for (int j = 0; j < 8; j++){
            int col = (j < 4) ? (cx*4 + j) : (128 + cx*4 + (j - 4));
            g_rv[((size_t)r*GG + row)*HH + col] = acc[i][j] + bp[r*HH + col];
        }
    }
}

// ---------------- 7: final MLP: LN -> SiLU -> Wf1 -> SiLU -> Wf2 ----------------
__global__ __launch_bounds__(256) void final_mlp(
    const float* __restrict__ ln_g, const float* __restrict__ ln_b,
    const float* __restrict__ Wf1,  const float* __restrict__ bf1,
    const float* __restrict__ Wf2,  const float* __restrict__ bf2,
    float* __restrict__ out)
{
    __shared__ float st[4][3*HH];   // state, then y=silu(LN(state)) in place
    __shared__ float ws[8], wq[8];
    __shared__ float red[4][8];

    const int tid  = threadIdx.x;
    const int lane = tid & 31;
    const int wrp  = tid >> 5;
    const int g0   = blockIdx.x * 4;

    for (int t = tid; t < 4*3*HH; t += 256){
        int gg = t / (3*HH);
        int k  = t - gg*3*HH;
        int r  = k >> 8;
        int j  = k & 255;
        st[gg][k] = g_rv[((size_t)r*GG + g0 + gg)*HH + j];
    }
    __syncthreads();

    // LayerNorm + first SiLU, per graph
    for (int gg = 0; gg < 4; gg++){
        float v0 = st[gg][tid], v1 = st[gg][tid + 256], v2 = st[gg][tid + 512];
        float sm = v0 + v1 + v2;
        float sq = v0*v0 + v1*v1 + v2*v2;
        #pragma unroll
        for (int o = 16; o > 0; o >>= 1){
            sm += __shfl_xor_sync(0xffffffffu, sm, o);
            sq += __shfl_xor_sync(0xffffffffu, sq, o);
        }
        if (lane == 0){ ws[wrp] = sm; wq[wrp] = sq; }
        __syncthreads();
        float tm = 0.f, tq = 0.f;
        #pragma unroll
        for (int w = 0; w < 8; w++){ tm += ws[w]; tq += wq[w]; }
        float mu   = tm / (3.f*HH);
        float var  = tq / (3.f*HH) - mu*mu;
        float rstd = rsqrtf(var + 1e-5f);
        st[gg][tid]       = siluf((v0 - mu)*rstd*ln_g[tid]       + ln_b[tid]);
        st[gg][tid + 256] = siluf((v1 - mu)*rstd*ln_g[tid + 256] + ln_b[tid + 256]);
        st[gg][tid + 512] = siluf((v2 - mu)*rstd*ln_g[tid + 512] + ln_b[tid + 512]);
        __syncthreads();
    }

    // z_j = silu(y @ Wf1 + bf1), then out = z @ Wf2 + bf2
    float acc[4];
    float bz = bf1[tid];
    #pragma unroll
    for (int gg = 0; gg < 4; gg++) acc[gg] = bz;
    for (int k = 0; k < 3*HH; k++){
        float w = Wf1[k*HH + tid];
        #pragma unroll
        for (int gg = 0; gg < 4; gg++) acc[gg] += st[gg][k] * w;
    }
    float w2v = Wf2[tid];
    #pragma unroll
    for (int gg = 0; gg < 4; gg++){
        float z = siluf(acc[gg]) * w2v;
        #pragma unroll
        for (int o = 16; o > 0; o >>= 1) z += __shfl_xor_sync(0xffffffffu, z, o);
        if (lane == 0) red[gg][wrp] = z;
    }
    __syncthreads();
    if (tid < 4){
        float o = bf2[0];
        #pragma unroll
        for (int w = 0; w < 8; w++) o += red[tid][w];
        out[g0 + tid] = o;
    }
}

// ---------------- launch ----------------
extern "C" void kernel_launch(void* const* d_in, const int* in_sizes, int n_in,
                              void* d_out, int out_size)
{
    const float* h     = (const float*)d_in[0];
    const int*   batch = (const int*)  d_in[1];
    const float* W1    = (const float*)d_in[2];
    const float* b1    = (const float*)d_in[3];
    const float* w2    = (const float*)d_in[4];
    const float* b2    = (const float*)d_in[5];
    const float* Wp    = (const float*)d_in[6];
    const float* bp    = (const float*)d_in[7];
    const float* ln_g  = (const float*)d_in[8];
    const float* ln_b  = (const float*)d_in[9];
    const float* Wf1   = (const float*)d_in[10];
    const float* bf1   = (const float*)d_in[11];
    const float* Wf2   = (const float*)d_in[12];
    const float* bf2   = (const float*)d_in[13];
    float* out = (float*)d_out;

    zero_kernel<<<(RK*GG*HH + 255)/256, 256>>>();
    score_gemm<<<dim3((NN + 63)/64, RK), 256>>>(h, W1, b1, w2, b2);
    seg_max_kernel<<<(TOT + 255)/256, 256>>>(batch);
    seg_exp_kernel<<<(TOT + 255)/256, 256>>>(batch);
    pool_kernel<<<(TOT + CHUNK - 1)/CHUNK, 256>>>(h, batch);
    finalize_kernel<<<(RK*GG*HH + 255)/256, 256>>>();
    rv_gemm<<<dim3(GG/64, RK), 256>>>(Wp, bp);
    final_mlp<<<GG/4, 256>>>(ln_g, ln_b, Wf1, bf1, Wf2, bf2, out);
}